// round 1
// baseline (speedup 1.0000x reference)
#include <cuda_runtime.h>
#include <math.h>

// ---------------- static config ----------------
constexpr int  Bn   = 4;
constexpr int  Ln   = 4096;
constexpr int  Dn   = 1024;
constexpr int  Kn   = 32;
constexpr int  Hn   = 32;
constexpr int  An   = 4;
constexpr int  CKn  = 4;
constexpr int  ZCn  = 2 * Dn + Kn;      // 2080
constexpr int  FLATn = Kn * Hn;         // 1024

// ---------------- scratch (device globals; no allocation allowed) ----------------
__device__ float g_z[(size_t)Bn * Ln * ZCn];        // in_proj output         (136 MB)
__device__ float g_merged[(size_t)Bn * Ln * ZCn];   // merged -> cumsum inplace (136 MB)
__device__ float g_gate[(size_t)Bn * Ln * Dn];      // silu gate              (64 MB)
__device__ float g_v[(size_t)Bn * Ln * Dn];         // y * gate               (64 MB)

// ---------------- generic fp32 tiled GEMM: C[M,N] = A[M,K] @ B[K,N], row-major ----
// M must be divisible by 128, K divisible by 8. N handled with guards.
__global__ __launch_bounds__(256)
void sgemm_kernel(const float* __restrict__ A, const float* __restrict__ B,
                  float* __restrict__ C, int M, int N, int K)
{
    constexpr int BM = 128, BN = 128, BK = 8, TM = 8, TN = 8;
    __shared__ float As[BK][BM];
    __shared__ float Bs[BK][BN];

    const int tid = threadIdx.x;
    const int bx = blockIdx.x;    // N tiles
    const int by = blockIdx.y;    // M tiles
    const int nBase = bx * BN;

    const int aRow = tid >> 1;           // 0..127
    const int aCol = (tid & 1) << 2;     // 0 or 4
    const int bRow = tid >> 5;           // 0..7
    const int bCol = (tid & 31) << 2;    // 0..124
    const int tx = tid & 15;
    const int ty = tid >> 4;
    const bool nFull = (nBase + BN) <= N;

    float acc[TM][TN];
#pragma unroll
    for (int i = 0; i < TM; i++)
#pragma unroll
        for (int j = 0; j < TN; j++) acc[i][j] = 0.f;

    const float* Ag = A + (size_t)(by * BM + aRow) * K;

    for (int k0 = 0; k0 < K; k0 += BK) {
        float4 a4 = *(const float4*)(Ag + k0 + aCol);
        As[aCol + 0][aRow] = a4.x;
        As[aCol + 1][aRow] = a4.y;
        As[aCol + 2][aRow] = a4.z;
        As[aCol + 3][aRow] = a4.w;

        if (nFull) {
            float4 b4 = *(const float4*)(B + (size_t)(k0 + bRow) * N + nBase + bCol);
            *(float4*)&Bs[bRow][bCol] = b4;
        } else {
#pragma unroll
            for (int t = 0; t < 4; t++) {
                int col = nBase + bCol + t;
                Bs[bRow][bCol + t] = (col < N) ? B[(size_t)(k0 + bRow) * N + col] : 0.f;
            }
        }
        __syncthreads();

#pragma unroll
        for (int kk = 0; kk < BK; kk++) {
            float ar[TM], br[TN];
#pragma unroll
            for (int i = 0; i < TM; i++) ar[i] = As[kk][ty * TM + i];
#pragma unroll
            for (int j = 0; j < TN; j++) br[j] = Bs[kk][tx * TN + j];
#pragma unroll
            for (int i = 0; i < TM; i++)
#pragma unroll
                for (int j = 0; j < TN; j++)
                    acc[i][j] += ar[i] * br[j];
        }
        __syncthreads();
    }

#pragma unroll
    for (int i = 0; i < TM; i++) {
        int row = by * BM + ty * TM + i;
        if (nFull) {
#pragma unroll
            for (int j = 0; j < TN; j += 4) {
                float4 o = make_float4(acc[i][j], acc[i][j + 1], acc[i][j + 2], acc[i][j + 3]);
                *(float4*)(C + (size_t)row * N + nBase + tx * TN + j) = o;
            }
        } else {
#pragma unroll
            for (int j = 0; j < TN; j++) {
                int col = nBase + tx * TN + j;
                if (col < N) C[(size_t)row * N + col] = acc[i][j];
            }
        }
    }
}

// ---------------- conv + feature construction ----------------
// per (b,l): causal depthwise conv on all ZC channels of g_z, then build
// merged = [p_w (32), p_w*cos(phi) (1024), p_w*sin(phi) (1024)] and gate = silu.
__global__ __launch_bounds__(256)
void feat_kernel(const float* __restrict__ Wc, const float* __restrict__ theta,
                 const float* __restrict__ decay, const float* __restrict__ anchor,
                 const float* __restrict__ sscale)
{
    const int l = blockIdx.x;
    const int b = blockIdx.y;
    const int tid = threadIdx.x;
    const size_t rowBase = ((size_t)b * Ln + l) * ZCn;

    __shared__ float s_pw[Kn];

    if (tid < Kn) {
        int c = 2 * Dn + tid;
        float a = 0.f;
#pragma unroll
        for (int j = 0; j < CKn; j++) {
            int ll = l - (CKn - 1) + j;
            if (ll >= 0) a += g_z[((size_t)b * Ln + ll) * ZCn + c] * Wc[j * ZCn + c];
        }
        float slope, lw;
        if (tid < Kn - An) {
            slope = log1pf(expf(decay[tid]));
            lw = -slope * (float)(Ln - 1 - l);
        } else {
            slope = log1pf(expf(anchor[tid - (Kn - An)]));
            lw = -slope * (float)l;
        }
        float pw = expf(sscale[tid] * a + lw);
        s_pw[tid] = pw;
        g_merged[rowBase + tid] = pw;
    }
    __syncthreads();

    for (int c = tid; c < 2 * Dn; c += 256) {
        float a = 0.f;
#pragma unroll
        for (int j = 0; j < CKn; j++) {
            int ll = l - (CKn - 1) + j;
            if (ll >= 0) a += g_z[((size_t)b * Ln + ll) * ZCn + c] * Wc[j * ZCn + c];
        }
        if (c < Dn) {
            float ph = a * theta[c];
            float sn, cn;
            sincosf(ph, &sn, &cn);
            float pw = s_pw[c >> 5];
            g_merged[rowBase + Kn + c]         = pw * cn;
            g_merged[rowBase + Kn + FLATn + c] = pw * sn;
        } else {
            int d = c - Dn;
            g_gate[((size_t)b * Ln + l) * Dn + d] = a / (1.f + expf(-a));   // silu
        }
    }
}

// ---------------- causal cumsum over L, per (b, channel), in place -------------
__global__ __launch_bounds__(256)
void scan_kernel()
{
    int idx = blockIdx.x * blockDim.x + threadIdx.x;
    if (idx >= Bn * ZCn) return;
    int b = idx / ZCn;
    int c = idx - b * ZCn;
    float* p = g_merged + (size_t)b * Ln * ZCn + c;
    float acc = 0.f;
    for (int l0 = 0; l0 < Ln; l0 += 8) {
        float v[8];
#pragma unroll
        for (int j = 0; j < 8; j++) v[j] = p[(size_t)(l0 + j) * ZCn];
#pragma unroll
        for (int j = 0; j < 8; j++) {
            acc += v[j];
            p[(size_t)(l0 + j) * ZCn] = acc;
        }
    }
}

// ---------------- per-(b,l,k): normalize, RMS, 32x32 head GEMM, gate ----------
__global__ __launch_bounds__(256)
void head_kernel(const float* __restrict__ Wre, const float* __restrict__ Wim,
                 const float* __restrict__ nscale)
{
    __shared__ float sWre[Hn * Hn];
    __shared__ float sWim[Hn * Hn];
    __shared__ float sNs[2 * Hn];

    const int tid = threadIdx.x;
    for (int i = tid; i < Hn * Hn; i += 256) { sWre[i] = Wre[i]; sWim[i] = Wim[i]; }
    if (tid < 2 * Hn) sNs[tid] = nscale[tid];
    __syncthreads();

    const int warp = tid >> 5;
    const int lane = tid & 31;
    const size_t gidx = (size_t)blockIdx.x * 8 + warp;   // over B*L*K
    const int k = (int)(gidx & (Kn - 1));
    const int l = (int)((gidx >> 5) & (Ln - 1));
    const int b = (int)(gidx >> 17);

    const size_t rowBase = ((size_t)b * Ln + l) * ZCn;
    const float den = g_merged[rowBase + k];
    const float inv = 1.f / fmaxf(den, 1e-4f);
    const float re = g_merged[rowBase + Kn + k * Hn + lane] * inv;
    const float im = g_merged[rowBase + Kn + FLATn + k * Hn + lane] * inv;

    float ss = re * re + im * im;
#pragma unroll
    for (int o = 16; o > 0; o >>= 1) ss += __shfl_xor_sync(0xffffffffu, ss, o);
    const float rs = rsqrtf(ss * (1.f / (2.f * Hn)) + 1e-5f);

    const float ar = re * rs * sNs[lane];
    const float ai = im * rs * sNs[Hn + lane];

    float y = 0.f;
#pragma unroll
    for (int h = 0; h < Hn; h++) {
        float rh = __shfl_sync(0xffffffffu, ar, h);
        float ih = __shfl_sync(0xffffffffu, ai, h);
        y += rh * sWre[h * Hn + lane] + ih * sWim[h * Hn + lane];
    }

    const size_t o = ((size_t)b * Ln + l) * Dn + k * Hn + lane;
    g_v[o] = y * g_gate[o];
}

// ---------------- launch ----------------
extern "C" void kernel_launch(void* const* d_in, const int* in_sizes, int n_in,
                              void* d_out, int out_size)
{
    const float* x      = (const float*)d_in[0];
    const float* W_in   = (const float*)d_in[1];
    const float* Wc     = (const float*)d_in[2];
    const float* theta  = (const float*)d_in[3];
    const float* decay  = (const float*)d_in[4];
    const float* anchor = (const float*)d_in[5];
    const float* sscale = (const float*)d_in[6];
    const float* Wre    = (const float*)d_in[7];
    const float* Wim    = (const float*)d_in[8];
    const float* nscale = (const float*)d_in[9];
    const float* Wout   = (const float*)d_in[10];
    float* out = (float*)d_out;

    float *zPtr, *vPtr;
    cudaGetSymbolAddress((void**)&zPtr, g_z);
    cudaGetSymbolAddress((void**)&vPtr, g_v);

    const int M = Bn * Ln;   // 16384

    // 1) z = x @ W_in   [16384,1024] @ [1024,2080]
    {
        dim3 grid((ZCn + 127) / 128, M / 128);
        sgemm_kernel<<<grid, 256>>>(x, W_in, zPtr, M, ZCn, Dn);
    }
    // 2) conv + features
    {
        dim3 grid(Ln, Bn);
        feat_kernel<<<grid, 256>>>(Wc, theta, decay, anchor, sscale);
    }
    // 3) causal cumsum (in place on g_merged)
    {
        int n = Bn * ZCn;
        scan_kernel<<<(n + 255) / 256, 256>>>();
    }
    // 4) per-head normalize + small GEMM + gate -> g_v
    {
        int totalWarps = Bn * Ln * Kn;        // 524288
        head_kernel<<<totalWarps / 8, 256>>>(Wre, Wim, nscale);
    }
    // 5) out = v @ W_out   [16384,1024] @ [1024,1024]
    {
        dim3 grid(Dn / 128, M / 128);
        sgemm_kernel<<<grid, 256>>>(vPtr, Wout, out, M, Dn, Dn);
    }
}

// round 12
// speedup vs baseline: 2.4460x; 2.4460x over previous
#include <cuda_runtime.h>
#include <cuda_bf16.h>
#include <cstdint>
#include <math.h>

// ---------------- static config ----------------
constexpr int  Bn   = 4;
constexpr int  Ln   = 4096;
constexpr int  Dn   = 1024;
constexpr int  Kn   = 32;
constexpr int  Hn   = 32;
constexpr int  An   = 4;
constexpr int  CKn  = 4;
constexpr int  ZCn  = 2 * Dn + Kn;      // 2080
constexpr int  ZCP  = 2176;             // padded to 17 * 128 for full GEMM tiles
constexpr int  FLATn = Kn * Hn;         // 1024
constexpr int  KDIM = 1024;

// ---------------- scratch (device globals; no allocation allowed) ----------------
__device__ __align__(128) float g_z[(size_t)Bn * Ln * ZCP];        // in_proj out (padded)
__device__ __align__(128) float g_merged[(size_t)Bn * Ln * ZCn];   // merged -> cumsum inplace
__device__ __align__(128) float g_gate[(size_t)Bn * Ln * Dn];      // silu gate
__device__ __align__(128) __nv_bfloat16 g_Ah[(size_t)Bn * Ln * Dn];   // A hi (x, then y*gate)
__device__ __align__(128) __nv_bfloat16 g_Al[(size_t)Bn * Ln * Dn];   // A lo
__device__ __align__(128) __nv_bfloat16 g_BinH[(size_t)ZCP * Dn];     // W_in^T hi [2176,1024]
__device__ __align__(128) __nv_bfloat16 g_BinL[(size_t)ZCP * Dn];
__device__ __align__(128) __nv_bfloat16 g_BoutH[(size_t)Dn * Dn];     // W_out^T hi
__device__ __align__(128) __nv_bfloat16 g_BoutL[(size_t)Dn * Dn];

// ================= helpers =================
__device__ __forceinline__ uint32_t smem_to_u32(const void* smem_ptr) {
    uint32_t addr;
    asm("{ .reg .u64 tmp; cvta.to.shared.u64 tmp, %1; cvt.u32.u64 %0, tmp; }"
        : "=r"(addr) : "l"(smem_ptr));
    return addr;
}
#define SMEM_SWIZZLE_128B(byte_offset) \
    ((byte_offset) ^ (((byte_offset) >> 3) & 0x70))

__device__ __forceinline__ void ldmatrix_x4(uint32_t* r, uint32_t addr) {
    asm volatile("ldmatrix.sync.aligned.m8n8.x4.shared.b16 {%0,%1,%2,%3}, [%4];"
                 : "=r"(r[0]), "=r"(r[1]), "=r"(r[2]), "=r"(r[3]) : "r"(addr));
}
__device__ __forceinline__ void mma16816(float* c, const uint32_t* a, const uint32_t* b) {
    asm volatile(
        "mma.sync.aligned.m16n8k16.row.col.f32.bf16.bf16.f32 "
        "{%0,%1,%2,%3}, {%4,%5,%6,%7}, {%8,%9}, {%0,%1,%2,%3};"
        : "+f"(c[0]), "+f"(c[1]), "+f"(c[2]), "+f"(c[3])
        : "r"(a[0]), "r"(a[1]), "r"(a[2]), "r"(a[3]), "r"(b[0]), "r"(b[1]));
}
__device__ __forceinline__ void cp_async16(uint32_t saddr, const void* gaddr) {
    asm volatile("cp.async.cg.shared.global [%0], [%1], 16;" :: "r"(saddr), "l"(gaddr));
}
__device__ __forceinline__ void cp_commit() {
    asm volatile("cp.async.commit_group;" ::: "memory");
}

// ================= mma.sync GEMM: C[M,N] = Ah*Bh + Ah*Bl + Al*Bh ==============
// A*: [M,1024] bf16 row-major (K-major). B*: [N,1024] bf16 row-major (pre-transposed
// weights, K-major). Tile 128x128, BK=64 (128B SW128 rows), 2-stage cp.async pipeline.
// 8 warps: warpM = wid&3 (32 rows each), warpN = wid>>2 (64 cols each).
constexpr int NCHUNK = KDIM / 64;               // 16
constexpr int TILE_B = 128 * 128;               // 16 KB per tile (128 rows x 128B)
constexpr int STAGE_B = 4 * TILE_B;             // Ah, Al, Bh, Bl
constexpr int SMEM_GEMM_BYTES = 2 * STAGE_B;    // 131072

__global__ __launch_bounds__(256)
void gemm_mma_bf16x3(const __nv_bfloat16* __restrict__ Ah, const __nv_bfloat16* __restrict__ Al,
                     const __nv_bfloat16* __restrict__ Bh, const __nv_bfloat16* __restrict__ Bl,
                     float* __restrict__ C, int ldc)
{
    extern __shared__ char smem[];
    const uint32_t sb = smem_to_u32(smem);
    const int tid  = threadIdx.x;
    const int wid  = tid >> 5;
    const int lane = tid & 31;
    const int m0 = blockIdx.y * 128;
    const int n0 = blockIdx.x * 128;
    const int warpM = wid & 3;
    const int warpN = wid >> 2;

    const char* gPtr[4];
    gPtr[0] = (const char*)(Ah + (size_t)m0 * KDIM);
    gPtr[1] = (const char*)(Al + (size_t)m0 * KDIM);
    gPtr[2] = (const char*)(Bh + (size_t)n0 * KDIM);
    gPtr[3] = (const char*)(Bl + (size_t)n0 * KDIM);

    // per-thread load geometry (16B granules): 4 iters x (row = t>>3, chunk = t&7)
    auto load_stage = [&](int c, int s) {
        const size_t kOff = (size_t)c * 128;           // 64 bf16 = 128 bytes
        const uint32_t sStage = sb + s * STAGE_B;
#pragma unroll
        for (int w = 0; w < 4; w++) {
            const char* g = gPtr[w] + kOff;
            const uint32_t sdst = sStage + w * TILE_B;
#pragma unroll
            for (int i = 0; i < 4; i++) {
                int t = tid + i * 256;
                int row = t >> 3;
                int ch  = (t & 7) << 4;
                cp_async16(sdst + SMEM_SWIZZLE_128B(row * 128 + ch),
                           g + (size_t)row * (KDIM * 2) + ch);
            }
        }
        cp_commit();
    };

    // ldmatrix lane geometry (offsets within a tile)
    //   A frag (m16k16): row = rBase + (lane&15), colByte = kk*32 + ((lane>>4)<<4)
    //   B frag pair:     row = nBase + ((lane>>4)<<3) + (lane&7), colByte = kk*32 + (((lane>>3)&1)<<4)
    const int aRow  = warpM * 32 + (lane & 15);
    const int aColX = (lane >> 4) << 4;
    const int bRow  = warpN * 64 + ((lane >> 4) << 3) + (lane & 7);
    const int bColX = ((lane >> 3) & 1) << 4;
    // swizzle: phys = row*128 + (colByte ^ ((row&7)<<4))
    const uint32_t aOff0 = (uint32_t)aRow * 128;          const uint32_t aXor = (uint32_t)((aRow & 7) << 4);
    const uint32_t aOff1 = (uint32_t)(aRow + 16) * 128;   const uint32_t aXor1 = (uint32_t)(((aRow + 16) & 7) << 4);
    const uint32_t bOff  = (uint32_t)bRow * 128;          const uint32_t bXor = (uint32_t)((bRow & 7) << 4);

    float acc[2][8][4];
#pragma unroll
    for (int i = 0; i < 2; i++)
#pragma unroll
        for (int j = 0; j < 8; j++)
#pragma unroll
            for (int q = 0; q < 4; q++) acc[i][j][q] = 0.f;

    load_stage(0, 0);

    for (int c = 0; c < NCHUNK; c++) {
        const int s = c & 1;
        if (c + 1 < NCHUNK) {
            load_stage(c + 1, s ^ 1);
            asm volatile("cp.async.wait_group 1;" ::: "memory");
        } else {
            asm volatile("cp.async.wait_group 0;" ::: "memory");
        }
        __syncthreads();

        const uint32_t sAh = sb + s * STAGE_B;
        const uint32_t sAl = sAh + TILE_B;
        const uint32_t sBh = sAh + 2 * TILE_B;
        const uint32_t sBl = sAh + 3 * TILE_B;

#pragma unroll
        for (int kk = 0; kk < 4; kk++) {
            const uint32_t aCol = (uint32_t)(kk * 32 + aColX);
            const uint32_t bCol = (uint32_t)(kk * 32 + bColX);
            uint32_t ah0[4], ah1[4], al0[4], al1[4];
            ldmatrix_x4(ah0, sAh + aOff0 + (aCol ^ aXor));
            ldmatrix_x4(ah1, sAh + aOff1 + (aCol ^ aXor1));
            ldmatrix_x4(al0, sAl + aOff0 + (aCol ^ aXor));
            ldmatrix_x4(al1, sAl + aOff1 + (aCol ^ aXor1));
#pragma unroll
            for (int nq = 0; nq < 4; nq++) {
                const uint32_t bo = bOff + 128u * 16u * nq + (bCol ^ bXor);
                uint32_t bh[4], bl[4];
                ldmatrix_x4(bh, sBh + bo);
                ldmatrix_x4(bl, sBl + bo);
                // n-group 0 (b regs 0..1), n-group 1 (b regs 2..3)
                mma16816(acc[0][nq * 2],     ah0, bh);
                mma16816(acc[0][nq * 2],     ah0, bl);
                mma16816(acc[0][nq * 2],     al0, bh);
                mma16816(acc[0][nq * 2 + 1], ah0, bh + 2);
                mma16816(acc[0][nq * 2 + 1], ah0, bl + 2);
                mma16816(acc[0][nq * 2 + 1], al0, bh + 2);
                mma16816(acc[1][nq * 2],     ah1, bh);
                mma16816(acc[1][nq * 2],     ah1, bl);
                mma16816(acc[1][nq * 2],     al1, bh);
                mma16816(acc[1][nq * 2 + 1], ah1, bh + 2);
                mma16816(acc[1][nq * 2 + 1], ah1, bl + 2);
                mma16816(acc[1][nq * 2 + 1], al1, bh + 2);
            }
        }
        __syncthreads();
    }

    // epilogue: c0,c1 -> (r, col..col+1); c2,c3 -> (r+8, col..col+1)
    const int rBase = m0 + warpM * 32 + (lane >> 2);
    const int cBase = n0 + warpN * 64 + 2 * (lane & 3);
#pragma unroll
    for (int mi = 0; mi < 2; mi++) {
#pragma unroll
        for (int ni = 0; ni < 8; ni++) {
            const int r = rBase + mi * 16;
            const int col = cBase + ni * 8;
            *(float2*)(C + (size_t)r * ldc + col)       = make_float2(acc[mi][ni][0], acc[mi][ni][1]);
            *(float2*)(C + (size_t)(r + 8) * ldc + col) = make_float2(acc[mi][ni][2], acc[mi][ni][3]);
        }
    }
}

// ---------------- fp32 -> bf16 hi/lo split (elementwise) ----------------
__global__ __launch_bounds__(256)
void split_kernel(const float4* __restrict__ src, __nv_bfloat162* __restrict__ hi,
                  __nv_bfloat162* __restrict__ lo, int n4)
{
    int i = blockIdx.x * 256 + threadIdx.x;
    if (i >= n4) return;
    float4 v = src[i];
    __nv_bfloat16 h0 = __float2bfloat16(v.x);
    __nv_bfloat16 h1 = __float2bfloat16(v.y);
    __nv_bfloat16 h2 = __float2bfloat16(v.z);
    __nv_bfloat16 h3 = __float2bfloat16(v.w);
    hi[2 * i]     = __halves2bfloat162(h0, h1);
    hi[2 * i + 1] = __halves2bfloat162(h2, h3);
    lo[2 * i]     = __halves2bfloat162(__float2bfloat16(v.x - __bfloat162float(h0)),
                                       __float2bfloat16(v.y - __bfloat162float(h1)));
    lo[2 * i + 1] = __halves2bfloat162(__float2bfloat16(v.z - __bfloat162float(h2)),
                                       __float2bfloat16(v.w - __bfloat162float(h3)));
}

// ---------------- weight transpose + split: W[K,Nsrc] -> Bt[Nout,K] ----------
__global__ __launch_bounds__(256)
void wsplit_kernel(const float* __restrict__ W, __nv_bfloat16* __restrict__ hi,
                   __nv_bfloat16* __restrict__ lo, int Ksrc, int Nsrc, int Nout)
{
    size_t idx = (size_t)blockIdx.x * 256 + threadIdx.x;
    if (idx >= (size_t)Nout * Ksrc) return;
    int n = (int)(idx / Ksrc);
    int k = (int)(idx - (size_t)n * Ksrc);
    float v = (n < Nsrc) ? W[(size_t)k * Nsrc + n] : 0.f;
    __nv_bfloat16 h = __float2bfloat16(v);
    hi[idx] = h;
    lo[idx] = __float2bfloat16(v - __bfloat162float(h));
}

// ---------------- conv + feature construction ----------------
__global__ __launch_bounds__(256)
void feat_kernel(const float* __restrict__ Wc, const float* __restrict__ theta,
                 const float* __restrict__ decay, const float* __restrict__ anchor,
                 const float* __restrict__ sscale)
{
    const int l = blockIdx.x;
    const int b = blockIdx.y;
    const int tid = threadIdx.x;
    const size_t mrgBase = ((size_t)b * Ln + l) * ZCn;

    __shared__ float s_pw[Kn];

    if (tid < Kn) {
        int c = 2 * Dn + tid;
        float a = 0.f;
#pragma unroll
        for (int j = 0; j < CKn; j++) {
            int ll = l - (CKn - 1) + j;
            if (ll >= 0) a += g_z[((size_t)b * Ln + ll) * ZCP + c] * Wc[j * ZCn + c];
        }
        float slope, lw;
        if (tid < Kn - An) {
            slope = log1pf(expf(decay[tid]));
            lw = -slope * (float)(Ln - 1 - l);
        } else {
            slope = log1pf(expf(anchor[tid - (Kn - An)]));
            lw = -slope * (float)l;
        }
        float pw = expf(sscale[tid] * a + lw);
        s_pw[tid] = pw;
        g_merged[mrgBase + tid] = pw;
    }
    __syncthreads();

    for (int c = tid; c < 2 * Dn; c += 256) {
        float a = 0.f;
#pragma unroll
        for (int j = 0; j < CKn; j++) {
            int ll = l - (CKn - 1) + j;
            if (ll >= 0) a += g_z[((size_t)b * Ln + ll) * ZCP + c] * Wc[j * ZCn + c];
        }
        if (c < Dn) {
            float ph = a * theta[c];
            float sn, cn;
            sincosf(ph, &sn, &cn);
            float pw = s_pw[c >> 5];
            g_merged[mrgBase + Kn + c]         = pw * cn;
            g_merged[mrgBase + Kn + FLATn + c] = pw * sn;
        } else {
            int d = c - Dn;
            g_gate[((size_t)b * Ln + l) * Dn + d] = a / (1.f + expf(-a));   // silu
        }
    }
}

// ---------------- causal cumsum over L, per (b, channel), in place -------------
__global__ __launch_bounds__(256)
void scan_kernel()
{
    int idx = blockIdx.x * blockDim.x + threadIdx.x;
    if (idx >= Bn * ZCn) return;
    int b = idx / ZCn;
    int c = idx - b * ZCn;
    float* p = g_merged + (size_t)b * Ln * ZCn + c;
    float acc = 0.f;
    for (int l0 = 0; l0 < Ln; l0 += 8) {
        float v[8];
#pragma unroll
        for (int j = 0; j < 8; j++) v[j] = p[(size_t)(l0 + j) * ZCn];
#pragma unroll
        for (int j = 0; j < 8; j++) {
            acc += v[j];
            p[(size_t)(l0 + j) * ZCn] = acc;
        }
    }
}

// ---------------- per-(b,l,k): normalize, RMS, 32x32 head GEMM, gate ----------
// writes bf16 hi/lo of (y * gate) directly (fused split for the out-proj GEMM)
__global__ __launch_bounds__(256)
void head_kernel(const float* __restrict__ Wre, const float* __restrict__ Wim,
                 const float* __restrict__ nscale)
{
    __shared__ float sWre[Hn * Hn];
    __shared__ float sWim[Hn * Hn];
    __shared__ float sNs[2 * Hn];
    __shared__ float sAr[8][Hn];
    __shared__ float sAi[8][Hn];

    const int tid = threadIdx.x;
    for (int i = tid; i < Hn * Hn; i += 256) { sWre[i] = Wre[i]; sWim[i] = Wim[i]; }
    if (tid < 2 * Hn) sNs[tid] = nscale[tid];
    __syncthreads();

    const int warp = tid >> 5;
    const int lane = tid & 31;
    const size_t gidx = (size_t)blockIdx.x * 8 + warp;   // over B*L*K
    const int k = (int)(gidx & (Kn - 1));
    const int l = (int)((gidx >> 5) & (Ln - 1));
    const int b = (int)(gidx >> 17);

    const size_t rowBase = ((size_t)b * Ln + l) * ZCn;
    const float den = g_merged[rowBase + k];
    const float inv = 1.f / fmaxf(den, 1e-4f);
    const float re = g_merged[rowBase + Kn + k * Hn + lane] * inv;
    const float im = g_merged[rowBase + Kn + FLATn + k * Hn + lane] * inv;

    float ss = re * re + im * im;
#pragma unroll
    for (int o = 16; o > 0; o >>= 1) ss += __shfl_xor_sync(0xffffffffu, ss, o);
    const float rs = rsqrtf(ss * (1.f / (2.f * Hn)) + 1e-5f);

    sAr[warp][lane] = re * rs * sNs[lane];
    sAi[warp][lane] = im * rs * sNs[Hn + lane];
    __syncwarp();

    float y = 0.f;
#pragma unroll
    for (int h = 0; h < Hn; h += 4) {
#pragma unroll
        for (int u = 0; u < 4; u++) {
            y += sAr[warp][h + u] * sWre[(h + u) * Hn + lane]
               + sAi[warp][h + u] * sWim[(h + u) * Hn + lane];
        }
    }

    const size_t o = ((size_t)b * Ln + l) * Dn + k * Hn + lane;
    const float yo = y * g_gate[o];
    const __nv_bfloat16 h = __float2bfloat16(yo);
    g_Ah[o] = h;
    g_Al[o] = __float2bfloat16(yo - __bfloat162float(h));
}

// ---------------- launch ----------------
extern "C" void kernel_launch(void* const* d_in, const int* in_sizes, int n_in,
                              void* d_out, int out_size)
{
    const float* x      = (const float*)d_in[0];
    const float* W_in   = (const float*)d_in[1];
    const float* Wc     = (const float*)d_in[2];
    const float* theta  = (const float*)d_in[3];
    const float* decay  = (const float*)d_in[4];
    const float* anchor = (const float*)d_in[5];
    const float* sscale = (const float*)d_in[6];
    const float* Wre    = (const float*)d_in[7];
    const float* Wim    = (const float*)d_in[8];
    const float* nscale = (const float*)d_in[9];
    const float* Wout   = (const float*)d_in[10];
    float* out = (float*)d_out;

    float *zPtr;
    __nv_bfloat16 *ahPtr, *alPtr, *binH, *binL, *boutH, *boutL;
    cudaGetSymbolAddress((void**)&zPtr,  g_z);
    cudaGetSymbolAddress((void**)&ahPtr, g_Ah);
    cudaGetSymbolAddress((void**)&alPtr, g_Al);
    cudaGetSymbolAddress((void**)&binH,  g_BinH);
    cudaGetSymbolAddress((void**)&binL,  g_BinL);
    cudaGetSymbolAddress((void**)&boutH, g_BoutH);
    cudaGetSymbolAddress((void**)&boutL, g_BoutL);

    cudaFuncSetAttribute(gemm_mma_bf16x3, cudaFuncAttributeMaxDynamicSharedMemorySize,
                         SMEM_GEMM_BYTES);

    const int M = Bn * Ln;   // 16384

    // 0) weight transpose+split and x split
    {
        size_t nWin = (size_t)ZCP * Dn;
        wsplit_kernel<<<(unsigned)((nWin + 255) / 256), 256>>>(W_in, binH, binL, Dn, ZCn, ZCP);
        size_t nWout = (size_t)Dn * Dn;
        wsplit_kernel<<<(unsigned)((nWout + 255) / 256), 256>>>(Wout, boutH, boutL, Dn, Dn, Dn);
        int n4 = M * Dn / 4;
        split_kernel<<<(n4 + 255) / 256, 256>>>((const float4*)x,
                                                (__nv_bfloat162*)ahPtr, (__nv_bfloat162*)alPtr, n4);
    }
    // 1) z = x @ W_in   (mma.sync bf16x3)  [16384,1024] x [1024,2176pad]
    {
        dim3 grid(ZCP / 128, M / 128);
        gemm_mma_bf16x3<<<grid, 256, SMEM_GEMM_BYTES>>>(ahPtr, alPtr, binH, binL, zPtr, ZCP);
    }
    // 2) conv + features
    {
        dim3 grid(Ln, Bn);
        feat_kernel<<<grid, 256>>>(Wc, theta, decay, anchor, sscale);
    }
    // 3) causal cumsum (in place on g_merged)
    {
        int n = Bn * ZCn;
        scan_kernel<<<(n + 255) / 256, 256>>>();
    }
    // 4) per-head normalize + small GEMM + gate -> bf16 hi/lo (fused split)
    {
        int totalWarps = Bn * Ln * Kn;        // 524288
        head_kernel<<<totalWarps / 8, 256>>>(Wre, Wim, nscale);
    }
    // 5) out = (y*gate) @ W_out   (mma.sync bf16x3) [16384,1024] x [1024,1024]
    {
        dim3 grid(Dn / 128, M / 128);
        gemm_mma_bf16x3<<<grid, 256, SMEM_GEMM_BYTES>>>(ahPtr, alPtr, boutH, boutL, out, Dn);
    }
}